// round 15
// baseline (speedup 1.0000x reference)
#include <cuda_runtime.h>
#include <cuda_fp16.h>
#include <cstdint>

#define H_  128
#define W_  256
#define HW  32768
#define C_  64
#define CHW (C_*HW)          // 2,097,152
#define MOFF (2*CHW)         // out elements = 4,194,304

// ---------------- mma.sync / ldmatrix / cp.async helpers (sm_80+ PTX) --------
__device__ __forceinline__ uint32_t smem_u32(const void* p) {
    uint32_t a;
    asm("{ .reg .u64 t; cvta.to.shared.u64 t, %1; cvt.u32.u64 %0, t; }" : "=r"(a) : "l"(p));
    return a;
}
__device__ __forceinline__ void ldsm_x4(uint32_t* r, uint32_t addr) {
    asm volatile("ldmatrix.sync.aligned.m8n8.x4.shared.b16 {%0,%1,%2,%3}, [%4];"
        : "=r"(r[0]), "=r"(r[1]), "=r"(r[2]), "=r"(r[3]) : "r"(addr));
}
__device__ __forceinline__ void mma16816(float* d, const uint32_t* a, const uint32_t* b) {
    asm volatile("mma.sync.aligned.m16n8k16.row.col.f32.f16.f16.f32 "
        "{%0,%1,%2,%3}, {%4,%5,%6,%7}, {%8,%9}, {%0,%1,%2,%3};"
        : "+f"(d[0]), "+f"(d[1]), "+f"(d[2]), "+f"(d[3])
        : "r"(a[0]), "r"(a[1]), "r"(a[2]), "r"(a[3]), "r"(b[0]), "r"(b[1]));
}
#define CP16(dst, src, szr) \
    asm volatile("cp.async.cg.shared.global [%0], [%1], 16, %2;" \
        :: "r"(dst), "l"(src), "r"(szr) : "memory")
#define CP_WAIT_ALL() asm volatile("cp.async.wait_all;" ::: "memory")

// fp16 2-term split helpers: hi = rn(v), lo = rn(v - hi)
__device__ __forceinline__ uint32_t pack_hi(float v0, float v1, float& r0, float& r1) {
    __half h0 = __float2half_rn(v0);
    __half h1 = __float2half_rn(v1);
    r0 = v0 - __half2float(h0);
    r1 = v1 - __half2float(h1);
    return ((uint32_t)__half_as_ushort(h1) << 16) | __half_as_ushort(h0);
}
__device__ __forceinline__ uint32_t pack_lo(float r0, float r1) {
    return ((uint32_t)__half_as_ushort(__float2half_rn(r1)) << 16)
         | __half_as_ushort(__float2half_rn(r0));
}

// ---------------- scratch ----------------------------------------------------
__device__ __align__(16) __half g_in_hi [4*HW*C_];   // [img][y][x][ch]
__device__ __align__(16) __half g_in_lo [4*HW*C_];
__device__ __align__(16) __half g_mid_hi[4*HW*C_];
__device__ __align__(16) __half g_mid_lo[4*HW*C_];
__device__ __align__(16) __half g_buf_hi[4*HW*C_];   // residual block out
__device__ __align__(16) __half g_buf_lo[4*HW*C_];
__device__ __align__(16) __half g_att_hi[2*HW*C_];
__device__ __align__(16) __half g_att_lo[2*HW*C_];
__device__ __align__(16) __half g_w1B[9*4096];       // [tap][kc][oc][k16] frag-native
__device__ __align__(16) __half g_w2B[9*4096];
__device__ __align__(16) __half g_wq_hi [64*64];     // [oc][ic]
__device__ __align__(16) __half g_wsr_hi[128*64];    // S then R
__device__ __align__(16) __half g_wf_hi [64*128];    // fuse [oc][ic]
__device__ __align__(16) float g_Q[2*HW*C_];         // [p][c] fp32
__device__ __align__(16) float g_S[2*HW*C_];
__device__ __align__(16) float g_R[2*HW*C_];

// ---------------- prep: fp32 NCHW -> fp16 hi/lo [img][y][x][ch] --------------
__global__ __launch_bounds__(256)
void prep_kernel(const float* __restrict__ xl, const float* __restrict__ xr)
{
    const int gp = blockIdx.x*256 + threadIdx.x;   // 0..4*HW-1
    const int n  = gp >> 15, pix = gp & (HW-1);
    const float* src = ((n < 2) ? (xl + n*CHW) : (xr + (n-2)*CHW)) + pix;

    uint32_t hb[32], lb[32];
#pragma unroll
    for (int j = 0; j < 32; j++) {
        float v0 = src[(size_t)(2*j)*HW];
        float v1 = src[(size_t)(2*j+1)*HW];
        float r0, r1;
        hb[j] = pack_hi(v0, v1, r0, r1);
        lb[j] = pack_lo(r0, r1);
    }
    uint4* dh = reinterpret_cast<uint4*>(g_in_hi + (size_t)gp*64);
    uint4* dl = reinterpret_cast<uint4*>(g_in_lo + (size_t)gp*64);
    const uint4* sh = reinterpret_cast<const uint4*>(hb);
    const uint4* sl = reinterpret_cast<const uint4*>(lb);
#pragma unroll
    for (int j = 0; j < 8; j++) { dh[j] = sh[j]; dl[j] = sl[j]; }
}

// ---------------- prep all weights (conv1, conv2, Q, S, R, fuse) -------------
__global__ __launch_bounds__(256)
void prep_w_all(const float* __restrict__ w1, const float* __restrict__ w2,
                const float* __restrict__ qw, const float* __restrict__ sw,
                const float* __restrict__ rw, const float* __restrict__ fw)
{
    const int i = blockIdx.x*256 + threadIdx.x;
    if (i < 9*4096) {
        const int tap = i >> 12, r = i & 4095;
        const int oc = r >> 6, ci = r & 63;
        const int kc = ci >> 4, kk = ci & 15;
        const int src = (oc*64 + ci)*9 + tap;
        const int dst = ((tap*4 + kc)*64 + oc)*16 + kk;   // frag-native
        g_w1B[dst] = __float2half_rn(w1[src]);
        g_w2B[dst] = __float2half_rn(w2[src]);
    } else {
        const int j = i - 9*4096;
        if (j >= 20480) return;
        if (j < 4096)       g_wq_hi [j]             = __float2half_rn(qw[j]);
        else if (j < 8192)  g_wsr_hi[j - 4096]      = __float2half_rn(sw[j - 4096]);
        else if (j < 12288) g_wsr_hi[4096 + j-8192] = __float2half_rn(rw[j - 8192]);
        else                g_wf_hi [j - 12288]     = __float2half_rn(fw[j - 12288]);
    }
}

// ---------------- HMMA 3x3 conv: rolling A ring, B frags via LDG -------------
// CTA = 256 thr (8 warps: 4 M x 2 N), strip = 64 px, segment = 4 rows (2 pairs)
#define APX2  66
#define AROW2 (APX2*128)               // 8448 bytes per plane per half
#define CA_HI 0u
#define CA_LO (4u*AROW2)               // 33792
#define SMEM_CONV (8u*AROW2)           // 67584  (A ring only)

__global__ __launch_bounds__(256, 3)
void conv_mma_kernel(const __half* __restrict__ in_hi,
                     const __half* __restrict__ in_lo,
                     const uint32_t* __restrict__ wB,
                     const float* __restrict__ xl, const float* __restrict__ xr,
                     int layer)
{
    extern __shared__ __align__(16) char smem[];
    const uint32_t sb = smem_u32(smem);
    const int tid = threadIdx.x;
    const int lane = tid & 31, warp = tid >> 5;
    const int wm = warp & 3, wn = warp >> 2;
    const int mbase = wm*16, ocb = wn*32;
    const int grp = lane >> 3, row = lane & 7;

    const int cta = blockIdx.x;           // 512 CTAs = img(4) x strip(4) x seg(32)
    const int n  = cta >> 7;
    const int x0 = ((cta >> 5) & 3) * 64;
    const int y0 = (cta & 31) * 4;

    // async stage one input row gy into plane (gy+4)&3 (ignore-src zero fill OOB)
    auto stage_row = [&](int gy) {
        const uint32_t pl = (uint32_t)((gy + 4) & 3) * AROW2;
        const int cy = gy < 0 ? 0 : (gy >= H_ ? H_-1 : gy);
        for (int i = tid; i < 528; i += 256) {
            const int px = i >> 3, g = i & 7;
            const int gx = x0 + px - 1;
            const bool ok = ((unsigned)gy < (unsigned)H_) && ((unsigned)gx < (unsigned)W_);
            const int cx = gx < 0 ? 0 : (gx >= W_ ? W_-1 : gx);
            const size_t go = (((size_t)(n*H_ + cy))*W_ + cx)*64 + g*8;
            const uint32_t da = pl + px*128 + ((g ^ (px & 7)) << 4);
            const uint32_t sz = ok ? 16u : 0u;
            CP16(sb + CA_HI + da, in_hi + go, sz);
            CP16(sb + CA_LO + da, in_lo + go, sz);
        }
    };

    stage_row(y0 - 1); stage_row(y0); stage_row(y0 + 1); stage_row(y0 + 2);
    CP_WAIT_ALL();
    __syncthreads();

    for (int p = 0; p < 2; p++) {
        const int yp = y0 + 2*p;

        float d[2][4][4];
#pragma unroll
        for (int t2 = 0; t2 < 2; t2++)
#pragma unroll
            for (int f = 0; f < 4; f++)
#pragma unroll
                for (int j = 0; j < 4; j++) d[t2][f][j] = 0.f;

        for (int tap = 0; tap < 9; tap++) {
            // prefetch next pair's rows; barrier protects the ring plane
            // being overwritten (last read at taps 2 / 5 respectively)
            if (p < 1 && tap == 3) { __syncthreads(); stage_row(yp + 3); }
            if (p < 1 && tap == 6) { __syncthreads(); stage_row(yp + 4); }

            const int dy = tap/3 - 1, dx = tap%3 - 1;

#pragma unroll
            for (int ks = 0; ks < 4; ks++) {
                // B fragments straight from global (frag-native layout, L1/L2-hot)
                uint32_t Bh[8];
                {
                    const uint32_t kbase = (uint32_t)((tap*4 + ks)*64 + ocb)*8;
#pragma unroll
                    for (int fr = 0; fr < 4; fr++) {
                        const uint32_t idx = kbase + (uint32_t)(fr*8 + (lane >> 2))*8 + (lane & 3);
                        Bh[2*fr]   = __ldg(wB + idx);
                        Bh[2*fr+1] = __ldg(wB + idx + 4);
                    }
                }
#pragma unroll
                for (int t2 = 0; t2 < 2; t2++) {
                    const uint32_t pl = (uint32_t)((yp + t2 + dy + 4) & 3) * AROW2;
                    const int m  = mbase + ((grp & 1) << 3) + row;
                    const int gA = 2*ks + (grp >> 1);
                    const int px = m + dx + 1;
                    const uint32_t aoff = pl + px*128u + ((gA ^ (px & 7)) << 4);
                    uint32_t Ah[4], Al[4];
                    ldsm_x4(Ah, sb + CA_HI + aoff);
                    ldsm_x4(Al, sb + CA_LO + aoff);
#pragma unroll
                    for (int f = 0; f < 4; f++) {
                        mma16816(d[t2][f], Ah, Bh + 2*f);
                        mma16816(d[t2][f], Al, Bh + 2*f);
                    }
                }
            }
        }
        CP_WAIT_ALL();
        __syncthreads();

        // ---- epilogue (registers -> global; no smem) ------------------------
        const int mrow = (lane >> 2);
        const int cpair = 2*(lane & 3);
#pragma unroll
        for (int t2 = 0; t2 < 2; t2++) {
            const int y = yp + t2;
            if (layer == 0) {
#pragma unroll
                for (int f = 0; f < 4; f++) {
#pragma unroll
                    for (int half = 0; half < 2; half++) {
                        float v0 = d[t2][f][2*half+0], v1 = d[t2][f][2*half+1];
                        v0 = v0 > 0.f ? v0 : 0.1f*v0;
                        v1 = v1 > 0.f ? v1 : 0.1f*v1;
                        const int m = mbase + mrow + half*8;
                        const int c = ocb + f*8 + cpair;
                        const size_t o = (((size_t)(n*H_ + y))*W_ + x0 + m)*64 + c;
                        float r0, r1;
                        *reinterpret_cast<uint32_t*>(g_mid_hi + o) = pack_hi(v0, v1, r0, r1);
                        *reinterpret_cast<uint32_t*>(g_mid_lo + o) = pack_lo(r0, r1);
                    }
                }
            } else {
                const float* res = (n < 2) ? (xl + n*CHW) : (xr + (n-2)*CHW);
#pragma unroll
                for (int f = 0; f < 4; f++) {
#pragma unroll
                    for (int half = 0; half < 2; half++) {
                        const int m = mbase + mrow + half*8;
                        const int c = ocb + f*8 + cpair;
                        const int pix = y*W_ + x0 + m;
                        float v0 = d[t2][f][2*half+0] + res[(size_t)c*HW + pix];
                        float v1 = d[t2][f][2*half+1] + res[(size_t)(c+1)*HW + pix];
                        const size_t o = ((size_t)n*HW + pix)*64 + c;
                        float r0, r1;
                        *reinterpret_cast<uint32_t*>(g_buf_hi + o) = pack_hi(v0, v1, r0, r1);
                        *reinterpret_cast<uint32_t*>(g_buf_lo + o) = pack_lo(r0, r1);
                    }
                }
            }
        }
    }
}

// ---------------- generic HMMA GEMM: [65536 px] x NOC oc, K=64 ---------------
#define QA_HI 0u
#define QA_LO 16384u
#define QB_HI 32768u
#define SMEM_GEMM 49152u

template<int NOC>
__global__ __launch_bounds__(512, 2)
void gemm_hmma(const __half* __restrict__ a_hi,
               const __half* __restrict__ a_lo,
               const __half* __restrict__ w_hi,
               const float* __restrict__ biasA, const float* __restrict__ biasB,
               float* __restrict__ outA, float* __restrict__ outB)
{
    extern __shared__ __align__(16) char smem[];
    const uint32_t sb = smem_u32(smem);
    const int tid = threadIdx.x;
    const int lane = tid & 31, warp = tid >> 5;
    const int wm = warp & 3, wn = warp >> 2;
    constexpr int NW  = NOC/4;
    constexpr int L16 = NW/16;
    constexpr int F8  = NW/8;
    const int mbase = wm*32, ocb = wn*NW;
    const int grp = lane >> 3, row = lane & 7;
    const int p0 = blockIdx.x * 128;

    for (int i = tid; i < 1024; i += 512) {
        const int px = i >> 3, g = i & 7;
        const uint32_t da = px*128 + ((g ^ (px & 7)) << 4);
        const size_t so = (size_t)(p0+px)*64 + g*8;
        CP16(sb + QA_HI + da, a_hi + so, 16u);
        CP16(sb + QA_LO + da, a_lo + so, 16u);
    }
    for (int i = tid; i < NOC*8; i += 512) {
        const int oc = i >> 3, g = i & 7;
        const uint32_t da = oc*128 + ((g ^ (oc & 7)) << 4);
        const size_t so = (size_t)oc*64 + g*8;
        CP16(sb + QB_HI + da, w_hi + so, 16u);
    }
    CP_WAIT_ALL();
    __syncthreads();

    float d[2][F8][4];
#pragma unroll
    for (int mt = 0; mt < 2; mt++)
#pragma unroll
        for (int f = 0; f < F8; f++)
#pragma unroll
            for (int j = 0; j < 4; j++) d[mt][f][j] = 0.f;

#pragma unroll
    for (int ks = 0; ks < 4; ks++) {
        uint32_t Bh[4*L16];
#pragma unroll
        for (int l = 0; l < L16; l++) {
            const int oc = ocb + l*16 + ((grp >> 1) << 3) + row;
            const int g  = 2*ks + (grp & 1);
            const uint32_t a = oc*128u + ((g ^ (oc & 7)) << 4);
            ldsm_x4(Bh + 4*l, sb + QB_HI + a);
        }
#pragma unroll
        for (int mt = 0; mt < 2; mt++) {
            const int m = mbase + mt*16 + ((grp & 1) << 3) + row;
            const int g = 2*ks + (grp >> 1);
            const uint32_t a = m*128u + ((g ^ (m & 7)) << 4);
            uint32_t Ah[4], Al[4];
            ldsm_x4(Ah, sb + QA_HI + a);
            ldsm_x4(Al, sb + QA_LO + a);
#pragma unroll
            for (int f = 0; f < F8; f++) {
                mma16816(d[mt][f], Ah, Bh + 2*f);
                mma16816(d[mt][f], Al, Bh + 2*f);
            }
        }
    }

#pragma unroll
    for (int mt = 0; mt < 2; mt++) {
#pragma unroll
        for (int f = 0; f < F8; f++) {
#pragma unroll
            for (int half = 0; half < 2; half++) {
                const int m = mbase + mt*16 + (lane >> 2) + half*8;
                const int c = ocb + f*8 + 2*(lane & 3);
                const float* bias = (c < 64) ? biasA : biasB;
                const int col = c & 63;
                float v0 = d[mt][f][2*half+0] + bias[col];
                float v1 = d[mt][f][2*half+1] + bias[col+1];
                float* o = ((c < 64) ? outA : outB) + (size_t)(p0+m)*64 + col;
                *reinterpret_cast<float2*>(o) = make_float2(v0, v1);
            }
        }
    }
}

// ---------------- attention: warp per pixel, K = 16 --------------------------
__global__ __launch_bounds__(256)
void attn_kernel(const int* __restrict__ xxs, const int* __restrict__ yys,
                 float* __restrict__ outM)
{
    const unsigned FULL = 0xffffffffu;
    const int warp = threadIdx.x >> 5, lane = threadIdx.x & 31;
    const int gp = blockIdx.x*8 + warp;
    const int b  = gp >> 15;

    const float2 q = reinterpret_cast<const float2*>(g_Q + (size_t)gp*64)[lane];

    int idx = 0;
    if (lane < 16) {
        int i = gp*16 + lane;
        idx = xxs[i]*W_ + yys[i];
    }
    const float* Sb = g_S + (size_t)b*HW*64;
    const float* Rb = g_R + (size_t)b*HW*64;

    float myscore = -1e30f;
#pragma unroll
    for (int k = 0; k < 16; k++) {
        int id = __shfl_sync(FULL, idx, k);
        float2 kv = reinterpret_cast<const float2*>(Sb + (size_t)id*64)[lane];
        float s = q.x*kv.x + q.y*kv.y;
#pragma unroll
        for (int off = 16; off; off >>= 1) s += __shfl_xor_sync(FULL, s, off);
        if (lane == k) myscore = s;
    }
    float mx = myscore;
#pragma unroll
    for (int off = 8; off; off >>= 1) mx = fmaxf(mx, __shfl_xor_sync(FULL, mx, off));
    float e = expf(myscore - mx);
    float sum = e;
#pragma unroll
    for (int off = 8; off; off >>= 1) sum += __shfl_xor_sync(FULL, sum, off);
    float m = e / sum;

    float2 accv = make_float2(0.f, 0.f);
#pragma unroll
    for (int k = 0; k < 16; k++) {
        float mk = __shfl_sync(FULL, m, k);
        int   id = __shfl_sync(FULL, idx, k);
        float2 vv = reinterpret_cast<const float2*>(Rb + (size_t)id*64)[lane];
        accv.x = fmaf(mk, vv.x, accv.x);
        accv.y = fmaf(mk, vv.y, accv.y);
    }
    float r0, r1;
    const size_t o = (size_t)gp*64 + 2*lane;
    *reinterpret_cast<uint32_t*>(g_att_hi + o) = pack_hi(accv.x, accv.y, r0, r1);
    *reinterpret_cast<uint32_t*>(g_att_lo + o) = pack_lo(r0, r1);
    if (lane < 16) outM[(size_t)gp*16 + lane] = m;
}

// ---------------- fusion 1x1 HMMA: K=128 (attn 64 + x_left 64) -> 64 oc ------
#define FA_HI 0u
#define FA_LO 32768u
#define FB_HI 65536u
#define SMEM_FUSE 81920u

__global__ __launch_bounds__(512, 2)
void fuse_hmma(const float* __restrict__ fb, float* __restrict__ out)
{
    extern __shared__ __align__(16) char smem[];
    const uint32_t sb = smem_u32(smem);
    const int tid = threadIdx.x;
    const int lane = tid & 31, warp = tid >> 5;
    const int wm = warp & 3, wn = warp >> 2;
    const int mbase = wm*32, ocb = wn*16;
    const int grp = lane >> 3, row = lane & 7;
    const int p0 = blockIdx.x * 128;

    for (int i = tid; i < 2048; i += 512) {
        const int px = i >> 4, g = i & 15;
        const uint32_t da = px*256 + ((g ^ (px & 7)) << 4);
        const size_t so = (size_t)(p0+px)*64 + (g & 7)*8;
        const __half* sh = (g < 8) ? (g_att_hi + so) : (g_in_hi + so);
        const __half* sl = (g < 8) ? (g_att_lo + so) : (g_in_lo + so);
        CP16(sb + FA_HI + da, sh, 16u);
        CP16(sb + FA_LO + da, sl, 16u);
    }
    for (int i = tid; i < 1024; i += 512) {
        const int oc = i >> 4, g = i & 15;
        const uint32_t da = oc*256 + ((g ^ (oc & 7)) << 4);
        const size_t so = (size_t)oc*128 + g*8;
        CP16(sb + FB_HI + da, g_wf_hi + so, 16u);
    }
    CP_WAIT_ALL();
    __syncthreads();

    float d[2][2][4];
#pragma unroll
    for (int mt = 0; mt < 2; mt++)
#pragma unroll
        for (int f = 0; f < 2; f++)
#pragma unroll
            for (int j = 0; j < 4; j++) d[mt][f][j] = 0.f;

#pragma unroll
    for (int ks = 0; ks < 8; ks++) {
        uint32_t Bh[4];
        {
            const int oc = ocb + ((grp >> 1) << 3) + row;
            const int g  = 2*ks + (grp & 1);
            const uint32_t a = oc*256u + ((g ^ (oc & 7)) << 4);
            ldsm_x4(Bh, sb + FB_HI + a);
        }
#pragma unroll
        for (int mt = 0; mt < 2; mt++) {
            const int m = mbase + mt*16 + ((grp & 1) << 3) + row;
            const int g = 2*ks + (grp >> 1);
            const uint32_t a = m*256u + ((g ^ (m & 7)) << 4);
            uint32_t Ah[4], Al[4];
            ldsm_x4(Ah, sb + FA_HI + a);
            ldsm_x4(Al, sb + FA_LO + a);
#pragma unroll
            for (int f = 0; f < 2; f++) {
                mma16816(d[mt][f], Ah, Bh + 2*f);
                mma16816(d[mt][f], Al, Bh + 2*f);
            }
        }
    }
    __syncthreads();

    float* sf = reinterpret_cast<float*>(smem);    // [64][132]
#pragma unroll
    for (int mt = 0; mt < 2; mt++) {
#pragma unroll
        for (int f = 0; f < 2; f++) {
#pragma unroll
            for (int half = 0; half < 2; half++) {
                const int m = mbase + mt*16 + (lane >> 2) + half*8;
                const int c = ocb + f*8 + 2*(lane & 3);
                sf[(c+0)*132 + m] = d[mt][f][2*half+0];
                sf[(c+1)*132 + m] = d[mt][f][2*half+1];
            }
        }
    }
    __syncthreads();
    const int img = p0 >> 15, pix0 = p0 & (HW-1);
    for (int i = tid; i < 8192; i += 512) {
        const int c = i >> 7, px = i & 127;
        out[(size_t)img*CHW + (size_t)c*HW + pix0 + px] = sf[c*132 + px] + fb[c];
    }
}

// -----------------------------------------------------------------------------
extern "C" void kernel_launch(void* const* d_in, const int* in_sizes, int n_in,
                              void* d_out, int out_size)
{
    const float* xl    = (const float*)d_in[0];
    const float* xr    = (const float*)d_in[1];
    const int*   xxs   = (const int*)  d_in[2];
    const int*   yys   = (const int*)  d_in[3];
    const float* rb_w1 = (const float*)d_in[5];
    const float* rb_w2 = (const float*)d_in[6];
    const float* b1_w  = (const float*)d_in[7];
    const float* b1_b  = (const float*)d_in[8];
    const float* b2_w  = (const float*)d_in[9];
    const float* b2_b  = (const float*)d_in[10];
    const float* b3_w  = (const float*)d_in[11];
    const float* b3_b  = (const float*)d_in[12];
    const float* fus_w = (const float*)d_in[13];
    const float* fus_b = (const float*)d_in[14];
    float* out = (float*)d_out;

    static int attr_set = 0;
    if (!attr_set) {
        cudaFuncSetAttribute(conv_mma_kernel,
                             cudaFuncAttributeMaxDynamicSharedMemorySize, SMEM_CONV);
        cudaFuncSetAttribute(gemm_hmma<64>,
                             cudaFuncAttributeMaxDynamicSharedMemorySize, SMEM_GEMM);
        cudaFuncSetAttribute(gemm_hmma<128>,
                             cudaFuncAttributeMaxDynamicSharedMemorySize, SMEM_GEMM);
        cudaFuncSetAttribute(fuse_hmma,
                             cudaFuncAttributeMaxDynamicSharedMemorySize, SMEM_FUSE);
        attr_set = 1;
    }

    __half *p_in_hi, *p_in_lo, *p_mid_hi, *p_mid_lo;
    __half *p_w1B, *p_w2B;
    __half *p_bh, *p_bl, *p_wqh, *p_wsrh;
    float *p_Q, *p_S, *p_R;
    cudaGetSymbolAddress((void**)&p_in_hi,  g_in_hi);
    cudaGetSymbolAddress((void**)&p_in_lo,  g_in_lo);
    cudaGetSymbolAddress((void**)&p_mid_hi, g_mid_hi);
    cudaGetSymbolAddress((void**)&p_mid_lo, g_mid_lo);
    cudaGetSymbolAddress((void**)&p_w1B, g_w1B);
    cudaGetSymbolAddress((void**)&p_w2B, g_w2B);
    cudaGetSymbolAddress((void**)&p_bh,  g_buf_hi);
    cudaGetSymbolAddress((void**)&p_bl,  g_buf_lo);
    cudaGetSymbolAddress((void**)&p_wqh, g_wq_hi);
    cudaGetSymbolAddress((void**)&p_wsrh, g_wsr_hi);
    cudaGetSymbolAddress((void**)&p_Q, g_Q);
    cudaGetSymbolAddress((void**)&p_S, g_S);
    cudaGetSymbolAddress((void**)&p_R, g_R);

    prep_kernel<<<512, 256>>>(xl, xr);
    prep_w_all<<<224, 256>>>(rb_w1, rb_w2, b1_w, b2_w, b3_w, fus_w);

    conv_mma_kernel<<<512, 256, SMEM_CONV>>>(p_in_hi,  p_in_lo,
                                             (const uint32_t*)p_w1B, xl, xr, 0);
    conv_mma_kernel<<<512, 256, SMEM_CONV>>>(p_mid_hi, p_mid_lo,
                                             (const uint32_t*)p_w2B, xl, xr, 1);

    gemm_hmma<64> <<<512, 512, SMEM_GEMM>>>(p_bh, p_bl, p_wqh,
                                            b1_b, b1_b, p_Q, p_Q);
    gemm_hmma<128><<<512, 512, SMEM_GEMM>>>(p_bh + (size_t)2*HW*64, p_bl + (size_t)2*HW*64,
                                            p_wsrh, b2_b, b3_b, p_S, p_R);

    attn_kernel<<<8192, 256>>>(xxs, yys, out + MOFF);
    fuse_hmma<<<512, 512, SMEM_FUSE>>>(fus_b, out);
}

// round 16
// speedup vs baseline: 1.0529x; 1.0529x over previous
#include <cuda_runtime.h>
#include <cuda_fp16.h>
#include <cstdint>

#define H_  128
#define W_  256
#define HW  32768
#define C_  64
#define CHW (C_*HW)          // 2,097,152
#define MOFF (2*CHW)         // out elements = 4,194,304

// ---------------- mma.sync / ldmatrix / cp.async helpers (sm_80+ PTX) --------
__device__ __forceinline__ uint32_t smem_u32(const void* p) {
    uint32_t a;
    asm("{ .reg .u64 t; cvta.to.shared.u64 t, %1; cvt.u32.u64 %0, t; }" : "=r"(a) : "l"(p));
    return a;
}
__device__ __forceinline__ void ldsm_x4(uint32_t* r, uint32_t addr) {
    asm volatile("ldmatrix.sync.aligned.m8n8.x4.shared.b16 {%0,%1,%2,%3}, [%4];"
        : "=r"(r[0]), "=r"(r[1]), "=r"(r[2]), "=r"(r[3]) : "r"(addr));
}
__device__ __forceinline__ void mma16816(float* d, const uint32_t* a, const uint32_t* b) {
    asm volatile("mma.sync.aligned.m16n8k16.row.col.f32.f16.f16.f32 "
        "{%0,%1,%2,%3}, {%4,%5,%6,%7}, {%8,%9}, {%0,%1,%2,%3};"
        : "+f"(d[0]), "+f"(d[1]), "+f"(d[2]), "+f"(d[3])
        : "r"(a[0]), "r"(a[1]), "r"(a[2]), "r"(a[3]), "r"(b[0]), "r"(b[1]));
}
#define CP16(dst, src, szr) \
    asm volatile("cp.async.cg.shared.global [%0], [%1], 16, %2;" \
        :: "r"(dst), "l"(src), "r"(szr) : "memory")
#define CP_WAIT_ALL() asm volatile("cp.async.wait_all;" ::: "memory")

// fp16 2-term split helpers: hi = rn(v), lo = rn(v - hi)
__device__ __forceinline__ uint32_t pack_hi(float v0, float v1, float& r0, float& r1) {
    __half h0 = __float2half_rn(v0);
    __half h1 = __float2half_rn(v1);
    r0 = v0 - __half2float(h0);
    r1 = v1 - __half2float(h1);
    return ((uint32_t)__half_as_ushort(h1) << 16) | __half_as_ushort(h0);
}
__device__ __forceinline__ uint32_t pack_lo(float r0, float r1) {
    return ((uint32_t)__half_as_ushort(__float2half_rn(r1)) << 16)
         | __half_as_ushort(__float2half_rn(r0));
}

// ---------------- scratch ----------------------------------------------------
__device__ __align__(16) __half g_in_hi [4*HW*C_];   // [img][y][x][ch]
__device__ __align__(16) __half g_in_lo [4*HW*C_];
__device__ __align__(16) __half g_mid_hi[4*HW*C_];
__device__ __align__(16) __half g_mid_lo[4*HW*C_];
__device__ __align__(16) __half g_buf_hi[4*HW*C_];   // residual block out
__device__ __align__(16) __half g_buf_lo[4*HW*C_];
__device__ __align__(16) __half g_att_hi[2*HW*C_];
__device__ __align__(16) __half g_att_lo[2*HW*C_];
__device__ __align__(16) __half g_w1_hi[9*64*64];    // [tap][oc][ch]
__device__ __align__(16) __half g_w2_hi[9*64*64];
__device__ __align__(16) __half g_wq_hi [64*64];     // [oc][ic]
__device__ __align__(16) __half g_wsr_hi[128*64];    // S then R
__device__ __align__(16) __half g_wf_hi [64*128];    // fuse [oc][ic]
__device__ __align__(16) float g_Q[2*HW*C_];         // [p][c] fp32
__device__ __align__(16) float g_S[2*HW*C_];
__device__ __align__(16) float g_R[2*HW*C_];

// ---------------- prep (merged): inputs + all weights ------------------------
__global__ __launch_bounds__(256)
void prep_all(const float* __restrict__ xl, const float* __restrict__ xr,
              const float* __restrict__ w1, const float* __restrict__ w2,
              const float* __restrict__ qw, const float* __restrict__ sw,
              const float* __restrict__ rw, const float* __restrict__ fw)
{
    if (blockIdx.x < 512) {
        const int gp = blockIdx.x*256 + threadIdx.x;   // 0..4*HW-1
        const int n  = gp >> 15, pix = gp & (HW-1);
        const float* src = ((n < 2) ? (xl + n*CHW) : (xr + (n-2)*CHW)) + pix;

        uint32_t hb[32], lb[32];
#pragma unroll
        for (int j = 0; j < 32; j++) {
            float v0 = src[(size_t)(2*j)*HW];
            float v1 = src[(size_t)(2*j+1)*HW];
            float r0, r1;
            hb[j] = pack_hi(v0, v1, r0, r1);
            lb[j] = pack_lo(r0, r1);
        }
        uint4* dh = reinterpret_cast<uint4*>(g_in_hi + (size_t)gp*64);
        uint4* dl = reinterpret_cast<uint4*>(g_in_lo + (size_t)gp*64);
        const uint4* sh = reinterpret_cast<const uint4*>(hb);
        const uint4* sl = reinterpret_cast<const uint4*>(lb);
#pragma unroll
        for (int j = 0; j < 8; j++) { dh[j] = sh[j]; dl[j] = sl[j]; }
    } else {
        const int i = (blockIdx.x - 512)*256 + threadIdx.x;
        if (i < 9*4096) {
            const int tap = i >> 12, r = i & 4095;
            const int oc = r >> 6, ci = r & 63;
            const int src = (oc*64 + ci)*9 + tap;
            const int dst = (tap*64 + oc)*64 + ci;
            g_w1_hi[dst] = __float2half_rn(w1[src]);
            g_w2_hi[dst] = __float2half_rn(w2[src]);
        } else {
            const int j = i - 9*4096;
            if (j >= 20480) return;
            if (j < 4096)       g_wq_hi [j]             = __float2half_rn(qw[j]);
            else if (j < 8192)  g_wsr_hi[j - 4096]      = __float2half_rn(sw[j - 4096]);
            else if (j < 12288) g_wsr_hi[4096 + j-8192] = __float2half_rn(rw[j - 8192]);
            else                g_wf_hi [j - 12288]     = __float2half_rn(fw[j - 12288]);
        }
    }
}

// ---------------- HMMA 3x3 conv (R13 winner): ring + B ping-pong + cp.async --
// CTA = 256 thr (8 warps: 4 M x 2 N), strip = 64 px, segment = 8 rows (4 pairs)
#define APX2  66
#define AROW2 (APX2*128)               // 8448 bytes per plane per half
#define CA_HI 0u
#define CA_LO (4u*AROW2)               // 33792
#define CB_OFF (8u*AROW2)              // 67584
#define SMEM_CONV (CB_OFF + 16384u)    // 83968

__global__ __launch_bounds__(256, 2)
void conv_mma_kernel(const __half* __restrict__ in_hi,
                     const __half* __restrict__ in_lo,
                     const __half* __restrict__ w_hi,
                     const float* __restrict__ xl, const float* __restrict__ xr,
                     int layer)
{
    extern __shared__ __align__(16) char smem[];
    const uint32_t sb = smem_u32(smem);
    const int tid = threadIdx.x;
    const int lane = tid & 31, warp = tid >> 5;
    const int wm = warp & 3, wn = warp >> 2;
    const int mbase = wm*16, ocb = wn*32;
    const int grp = lane >> 3, row = lane & 7;

    const int cta = blockIdx.x;           // 256 CTAs = img(4) x strip(4) x seg(16)
    const int n  = cta >> 6;
    const int x0 = ((cta >> 4) & 3) * 64;
    const int y0 = (cta & 15) * 8;

    auto stage_row = [&](int gy) {
        const uint32_t pl = (uint32_t)((gy + 4) & 3) * AROW2;
        const int cy = gy < 0 ? 0 : (gy >= H_ ? H_-1 : gy);
        for (int i = tid; i < 528; i += 256) {
            const int px = i >> 3, g = i & 7;
            const int gx = x0 + px - 1;
            const bool ok = ((unsigned)gy < (unsigned)H_) && ((unsigned)gx < (unsigned)W_);
            const int cx = gx < 0 ? 0 : (gx >= W_ ? W_-1 : gx);
            const size_t go = (((size_t)(n*H_ + cy))*W_ + cx)*64 + g*8;
            const uint32_t da = pl + px*128 + ((g ^ (px & 7)) << 4);
            const uint32_t sz = ok ? 16u : 0u;
            CP16(sb + CA_HI + da, in_hi + go, sz);
            CP16(sb + CA_LO + da, in_lo + go, sz);
        }
    };
    auto stage_B = [&](int tap, int buf) {
        const uint32_t bdst = CB_OFF + (uint32_t)buf*8192u;
        for (int i = tid; i < 512; i += 256) {
            const int oc = i >> 3, g = i & 7;
            const uint32_t da = bdst + oc*128 + ((g ^ (oc & 7)) << 4);
            const size_t so = ((size_t)(tap*64 + oc))*64 + g*8;
            CP16(sb + da, w_hi + so, 16u);
        }
    };

    stage_row(y0 - 1); stage_row(y0); stage_row(y0 + 1); stage_row(y0 + 2);
    stage_B(0, 0);
    CP_WAIT_ALL();
    __syncthreads();

    for (int p = 0; p < 4; p++) {
        const int yp = y0 + 2*p;

        float d[2][4][4];
#pragma unroll
        for (int t2 = 0; t2 < 2; t2++)
#pragma unroll
            for (int f = 0; f < 4; f++)
#pragma unroll
                for (int j = 0; j < 4; j++) d[t2][f][j] = 0.f;

        for (int tap = 0; tap < 9; tap++) {
            // async prefetches: next tap's B; next pair's rows at taps 3 & 6
            stage_B((tap + 1) % 9, (p + tap + 1) & 1);
            if (p < 3 && tap == 3) stage_row(yp + 3);
            if (p < 3 && tap == 6) stage_row(yp + 4);

            const int dy = tap/3 - 1, dx = tap%3 - 1;
            const uint32_t bcur = CB_OFF + (uint32_t)((p + tap) & 1)*8192u;

#pragma unroll
            for (int ks = 0; ks < 4; ks++) {
                uint32_t Bh[8];
                {
                    const int oc0 = ocb + ((grp >> 1) << 3) + row;
                    const int gB  = 2*ks + (grp & 1);
                    const uint32_t a0 = oc0*128u + ((gB ^ (oc0 & 7)) << 4);
                    ldsm_x4(Bh,     sb + bcur + a0);
                    const int oc1 = oc0 + 16;
                    const uint32_t a1 = oc1*128u + ((gB ^ (oc1 & 7)) << 4);
                    ldsm_x4(Bh + 4, sb + bcur + a1);
                }
#pragma unroll
                for (int t2 = 0; t2 < 2; t2++) {
                    const uint32_t pl = (uint32_t)((yp + t2 + dy + 4) & 3) * AROW2;
                    const int m  = mbase + ((grp & 1) << 3) + row;
                    const int gA = 2*ks + (grp >> 1);
                    const int px = m + dx + 1;
                    const uint32_t aoff = pl + px*128u + ((gA ^ (px & 7)) << 4);
                    uint32_t Ah[4], Al[4];
                    ldsm_x4(Ah, sb + CA_HI + aoff);
                    ldsm_x4(Al, sb + CA_LO + aoff);
#pragma unroll
                    for (int f = 0; f < 4; f++) {
                        mma16816(d[t2][f], Ah, Bh + 2*f);
                        mma16816(d[t2][f], Al, Bh + 2*f);
                    }
                }
            }
            CP_WAIT_ALL();
            __syncthreads();
        }

        // ---- epilogue (registers -> global; no smem) ------------------------
        const int mrow = (lane >> 2);
        const int cpair = 2*(lane & 3);
#pragma unroll
        for (int t2 = 0; t2 < 2; t2++) {
            const int y = yp + t2;
            if (layer == 0) {
#pragma unroll
                for (int f = 0; f < 4; f++) {
#pragma unroll
                    for (int half = 0; half < 2; half++) {
                        float v0 = d[t2][f][2*half+0], v1 = d[t2][f][2*half+1];
                        v0 = v0 > 0.f ? v0 : 0.1f*v0;
                        v1 = v1 > 0.f ? v1 : 0.1f*v1;
                        const int m = mbase + mrow + half*8;
                        const int c = ocb + f*8 + cpair;
                        const size_t o = (((size_t)(n*H_ + y))*W_ + x0 + m)*64 + c;
                        float r0, r1;
                        *reinterpret_cast<uint32_t*>(g_mid_hi + o) = pack_hi(v0, v1, r0, r1);
                        *reinterpret_cast<uint32_t*>(g_mid_lo + o) = pack_lo(r0, r1);
                    }
                }
            } else {
                const float* res = (n < 2) ? (xl + n*CHW) : (xr + (n-2)*CHW);
#pragma unroll
                for (int f = 0; f < 4; f++) {
#pragma unroll
                    for (int half = 0; half < 2; half++) {
                        const int m = mbase + mrow + half*8;
                        const int c = ocb + f*8 + cpair;
                        const int pix = y*W_ + x0 + m;
                        float v0 = d[t2][f][2*half+0] + res[(size_t)c*HW + pix];
                        float v1 = d[t2][f][2*half+1] + res[(size_t)(c+1)*HW + pix];
                        const size_t o = ((size_t)n*HW + pix)*64 + c;
                        float r0, r1;
                        *reinterpret_cast<uint32_t*>(g_buf_hi + o) = pack_hi(v0, v1, r0, r1);
                        *reinterpret_cast<uint32_t*>(g_buf_lo + o) = pack_lo(r0, r1);
                    }
                }
            }
        }
    }
}

// ---------------- merged Q/S/R HMMA GEMM body (K=64) -------------------------
#define QA_HI 0u
#define QA_LO 16384u
#define QB_HI 32768u
#define SMEM_GEMM 49152u

template<int NOC>
__device__ __forceinline__
void gemm_body(char* smem, int bx,
               const __half* __restrict__ a_hi, const __half* __restrict__ a_lo,
               const __half* __restrict__ w_hi,
               const float* __restrict__ biasA, const float* __restrict__ biasB,
               float* __restrict__ outA, float* __restrict__ outB)
{
    const uint32_t sb = smem_u32(smem);
    const int tid = threadIdx.x;
    const int lane = tid & 31, warp = tid >> 5;
    const int wm = warp & 3, wn = warp >> 2;
    constexpr int NW  = NOC/4;
    constexpr int L16 = NW/16;
    constexpr int F8  = NW/8;
    const int mbase = wm*32, ocb = wn*NW;
    const int grp = lane >> 3, row = lane & 7;
    const int p0 = bx * 128;

    for (int i = tid; i < 1024; i += 512) {
        const int px = i >> 3, g = i & 7;
        const uint32_t da = px*128 + ((g ^ (px & 7)) << 4);
        const size_t so = (size_t)(p0+px)*64 + g*8;
        CP16(sb + QA_HI + da, a_hi + so, 16u);
        CP16(sb + QA_LO + da, a_lo + so, 16u);
    }
    for (int i = tid; i < NOC*8; i += 512) {
        const int oc = i >> 3, g = i & 7;
        const uint32_t da = oc*128 + ((g ^ (oc & 7)) << 4);
        const size_t so = (size_t)oc*64 + g*8;
        CP16(sb + QB_HI + da, w_hi + so, 16u);
    }
    CP_WAIT_ALL();
    __syncthreads();

    float d[2][F8][4];
#pragma unroll
    for (int mt = 0; mt < 2; mt++)
#pragma unroll
        for (int f = 0; f < F8; f++)
#pragma unroll
            for (int j = 0; j < 4; j++) d[mt][f][j] = 0.f;

#pragma unroll
    for (int ks = 0; ks < 4; ks++) {
        uint32_t Bh[4*L16];
#pragma unroll
        for (int l = 0; l < L16; l++) {
            const int oc = ocb + l*16 + ((grp >> 1) << 3) + row;
            const int g  = 2*ks + (grp & 1);
            const uint32_t a = oc*128u + ((g ^ (oc & 7)) << 4);
            ldsm_x4(Bh + 4*l, sb + QB_HI + a);
        }
#pragma unroll
        for (int mt = 0; mt < 2; mt++) {
            const int m = mbase + mt*16 + ((grp & 1) << 3) + row;
            const int g = 2*ks + (grp >> 1);
            const uint32_t a = m*128u + ((g ^ (m & 7)) << 4);
            uint32_t Ah[4], Al[4];
            ldsm_x4(Ah, sb + QA_HI + a);
            ldsm_x4(Al, sb + QA_LO + a);
#pragma unroll
            for (int f = 0; f < F8; f++) {
                mma16816(d[mt][f], Ah, Bh + 2*f);
                mma16816(d[mt][f], Al, Bh + 2*f);
            }
        }
    }

#pragma unroll
    for (int mt = 0; mt < 2; mt++) {
#pragma unroll
        for (int f = 0; f < F8; f++) {
#pragma unroll
            for (int half = 0; half < 2; half++) {
                const int m = mbase + mt*16 + (lane >> 2) + half*8;
                const int c = ocb + f*8 + 2*(lane & 3);
                const float* bias = (c < 64) ? biasA : biasB;
                const int col = c & 63;
                float v0 = d[mt][f][2*half+0] + bias[col];
                float v1 = d[mt][f][2*half+1] + bias[col+1];
                float* o = ((c < 64) ? outA : outB) + (size_t)(p0+m)*64 + col;
                *reinterpret_cast<float2*>(o) = make_float2(v0, v1);
            }
        }
    }
}

__global__ __launch_bounds__(512, 2)
void gemm_qsr(const __half* __restrict__ buf_hi, const __half* __restrict__ buf_lo,
              const __half* __restrict__ wq, const __half* __restrict__ wsr,
              const float* __restrict__ qb, const float* __restrict__ sbias,
              const float* __restrict__ rbias,
              float* __restrict__ Q, float* __restrict__ S, float* __restrict__ R)
{
    extern __shared__ __align__(16) char smem[];
    if (blockIdx.x < 512) {
        gemm_body<64>(smem, blockIdx.x, buf_hi, buf_lo, wq, qb, qb, Q, Q);
    } else {
        gemm_body<128>(smem, blockIdx.x - 512,
                       buf_hi + (size_t)2*HW*64, buf_lo + (size_t)2*HW*64,
                       wsr, sbias, rbias, S, R);
    }
}

// ---------------- attention: warp per pixel, K = 16 --------------------------
__global__ __launch_bounds__(256)
void attn_kernel(const int* __restrict__ xxs, const int* __restrict__ yys,
                 float* __restrict__ outM)
{
    const unsigned FULL = 0xffffffffu;
    const int warp = threadIdx.x >> 5, lane = threadIdx.x & 31;
    const int gp = blockIdx.x*8 + warp;
    const int b  = gp >> 15;

    const float2 q = reinterpret_cast<const float2*>(g_Q + (size_t)gp*64)[lane];

    int idx = 0;
    if (lane < 16) {
        int i = gp*16 + lane;
        idx = xxs[i]*W_ + yys[i];
    }
    const float* Sb = g_S + (size_t)b*HW*64;
    const float* Rb = g_R + (size_t)b*HW*64;

    float myscore = -1e30f;
#pragma unroll
    for (int k = 0; k < 16; k++) {
        int id = __shfl_sync(FULL, idx, k);
        float2 kv = reinterpret_cast<const float2*>(Sb + (size_t)id*64)[lane];
        float s = q.x*kv.x + q.y*kv.y;
#pragma unroll
        for (int off = 16; off; off >>= 1) s += __shfl_xor_sync(FULL, s, off);
        if (lane == k) myscore = s;
    }
    float mx = myscore;
#pragma unroll
    for (int off = 8; off; off >>= 1) mx = fmaxf(mx, __shfl_xor_sync(FULL, mx, off));
    float e = expf(myscore - mx);
    float sum = e;
#pragma unroll
    for (int off = 8; off; off >>= 1) sum += __shfl_xor_sync(FULL, sum, off);
    float m = e / sum;

    float2 accv = make_float2(0.f, 0.f);
#pragma unroll
    for (int k = 0; k < 16; k++) {
        float mk = __shfl_sync(FULL, m, k);
        int   id = __shfl_sync(FULL, idx, k);
        float2 vv = reinterpret_cast<const float2*>(Rb + (size_t)id*64)[lane];
        accv.x = fmaf(mk, vv.x, accv.x);
        accv.y = fmaf(mk, vv.y, accv.y);
    }
    float r0, r1;
    const size_t o = (size_t)gp*64 + 2*lane;
    *reinterpret_cast<uint32_t*>(g_att_hi + o) = pack_hi(accv.x, accv.y, r0, r1);
    *reinterpret_cast<uint32_t*>(g_att_lo + o) = pack_lo(r0, r1);
    if (lane < 16) outM[(size_t)gp*16 + lane] = m;
}

// ---------------- fusion 1x1 HMMA: K=128 (attn 64 + x_left 64) -> 64 oc ------
#define FA_HI 0u
#define FA_LO 32768u
#define FB_HI 65536u
#define SMEM_FUSE 81920u

__global__ __launch_bounds__(512, 2)
void fuse_hmma(const float* __restrict__ fb, float* __restrict__ out)
{
    extern __shared__ __align__(16) char smem[];
    const uint32_t sb = smem_u32(smem);
    const int tid = threadIdx.x;
    const int lane = tid & 31, warp = tid >> 5;
    const int wm = warp & 3, wn = warp >> 2;
    const int mbase = wm*32, ocb = wn*16;
    const int grp = lane >> 3, row = lane & 7;
    const int p0 = blockIdx.x * 128;

    for (int i = tid; i < 2048; i += 512) {
        const int px = i >> 4, g = i & 15;
        const uint32_t da = px*256 + ((g ^ (px & 7)) << 4);
        const size_t so = (size_t)(p0+px)*64 + (g & 7)*8;
        const __half* sh = (g < 8) ? (g_att_hi + so) : (g_in_hi + so);
        const __half* sl = (g < 8) ? (g_att_lo + so) : (g_in_lo + so);
        CP16(sb + FA_HI + da, sh, 16u);
        CP16(sb + FA_LO + da, sl, 16u);
    }
    for (int i = tid; i < 1024; i += 512) {
        const int oc = i >> 4, g = i & 15;
        const uint32_t da = oc*256 + ((g ^ (oc & 7)) << 4);
        const size_t so = (size_t)oc*128 + g*8;
        CP16(sb + FB_HI + da, g_wf_hi + so, 16u);
    }
    CP_WAIT_ALL();
    __syncthreads();

    float d[2][2][4];
#pragma unroll
    for (int mt = 0; mt < 2; mt++)
#pragma unroll
        for (int f = 0; f < 2; f++)
#pragma unroll
            for (int j = 0; j < 4; j++) d[mt][f][j] = 0.f;

#pragma unroll
    for (int ks = 0; ks < 8; ks++) {
        uint32_t Bh[4];
        {
            const int oc = ocb + ((grp >> 1) << 3) + row;
            const int g  = 2*ks + (grp & 1);
            const uint32_t a = oc*256u + ((g ^ (oc & 7)) << 4);
            ldsm_x4(Bh, sb + FB_HI + a);
        }
#pragma unroll
        for (int mt = 0; mt < 2; mt++) {
            const int m = mbase + mt*16 + ((grp & 1) << 3) + row;
            const int g = 2*ks + (grp >> 1);
            const uint32_t a = m*256u + ((g ^ (m & 7)) << 4);
            uint32_t Ah[4], Al[4];
            ldsm_x4(Ah, sb + FA_HI + a);
            ldsm_x4(Al, sb + FA_LO + a);
#pragma unroll
            for (int f = 0; f < 2; f++) {
                mma16816(d[mt][f], Ah, Bh + 2*f);
                mma16816(d[mt][f], Al, Bh + 2*f);
            }
        }
    }
    __syncthreads();

    float* sf = reinterpret_cast<float*>(smem);    // [64][132]
#pragma unroll
    for (int mt = 0; mt < 2; mt++) {
#pragma unroll
        for (int f = 0; f < 2; f++) {
#pragma unroll
            for (int half = 0; half < 2; half++) {
                const int m = mbase + mt*16 + (lane >> 2) + half*8;
                const int c = ocb + f*8 + 2*(lane & 3);
                sf[(c+0)*132 + m] = d[mt][f][2*half+0];
                sf[(c+1)*132 + m] = d[mt][f][2*half+1];
            }
        }
    }
    __syncthreads();
    const int img = p0 >> 15, pix0 = p0 & (HW-1);
    for (int i = tid; i < 8192; i += 512) {
        const int c = i >> 7, px = i & 127;
        out[(size_t)img*CHW + (size_t)c*HW + pix0 + px] = sf[c*132 + px] + fb[c];
    }
}

// -----------------------------------------------------------------------------
extern "C" void kernel_launch(void* const* d_in, const int* in_sizes, int n_in,
                              void* d_out, int out_size)
{
    const float* xl    = (const float*)d_in[0];
    const float* xr    = (const float*)d_in[1];
    const int*   xxs   = (const int*)  d_in[2];
    const int*   yys   = (const int*)  d_in[3];
    const float* rb_w1 = (const float*)d_in[5];
    const float* rb_w2 = (const float*)d_in[6];
    const float* b1_w  = (const float*)d_in[7];
    const float* b1_b  = (const float*)d_in[8];
    const float* b2_w  = (const float*)d_in[9];
    const float* b2_b  = (const float*)d_in[10];
    const float* b3_w  = (const float*)d_in[11];
    const float* b3_b  = (const float*)d_in[12];
    const float* fus_w = (const float*)d_in[13];
    const float* fus_b = (const float*)d_in[14];
    float* out = (float*)d_out;

    static int attr_set = 0;
    if (!attr_set) {
        cudaFuncSetAttribute(conv_mma_kernel,
                             cudaFuncAttributeMaxDynamicSharedMemorySize, SMEM_CONV);
        cudaFuncSetAttribute(gemm_qsr,
                             cudaFuncAttributeMaxDynamicSharedMemorySize, SMEM_GEMM);
        cudaFuncSetAttribute(fuse_hmma,
                             cudaFuncAttributeMaxDynamicSharedMemorySize, SMEM_FUSE);
        attr_set = 1;
    }

    __half *p_in_hi, *p_in_lo, *p_mid_hi, *p_mid_lo;
    __half *p_w1h, *p_w2h;
    __half *p_bh, *p_bl, *p_wqh, *p_wsrh;
    float *p_Q, *p_S, *p_R;
    cudaGetSymbolAddress((void**)&p_in_hi,  g_in_hi);
    cudaGetSymbolAddress((void**)&p_in_lo,  g_in_lo);
    cudaGetSymbolAddress((void**)&p_mid_hi, g_mid_hi);
    cudaGetSymbolAddress((void**)&p_mid_lo, g_mid_lo);
    cudaGetSymbolAddress((void**)&p_w1h, g_w1_hi);
    cudaGetSymbolAddress((void**)&p_w2h, g_w2_hi);
    cudaGetSymbolAddress((void**)&p_bh,  g_buf_hi);
    cudaGetSymbolAddress((void**)&p_bl,  g_buf_lo);
    cudaGetSymbolAddress((void**)&p_wqh, g_wq_hi);
    cudaGetSymbolAddress((void**)&p_wsrh, g_wsr_hi);
    cudaGetSymbolAddress((void**)&p_Q, g_Q);
    cudaGetSymbolAddress((void**)&p_S, g_S);
    cudaGetSymbolAddress((void**)&p_R, g_R);

    prep_all<<<736, 256>>>(xl, xr, rb_w1, rb_w2, b1_w, b2_w, b3_w, fus_w);

    conv_mma_kernel<<<256, 256, SMEM_CONV>>>(p_in_hi,  p_in_lo,  p_w1h, xl, xr, 0);
    conv_mma_kernel<<<256, 256, SMEM_CONV>>>(p_mid_hi, p_mid_lo, p_w2h, xl, xr, 1);

    gemm_qsr<<<1024, 512, SMEM_GEMM>>>(p_bh, p_bl, p_wqh, p_wsrh,
                                       b1_b, b2_b, b3_b, p_Q, p_S, p_R);

    attn_kernel<<<8192, 256>>>(xxs, yys, out + MOFF);
    fuse_hmma<<<512, 512, SMEM_FUSE>>>(fus_b, out);
}

// round 17
// speedup vs baseline: 1.0714x; 1.0176x over previous
#include <cuda_runtime.h>
#include <cuda_fp16.h>
#include <cstdint>

#define H_  128
#define W_  256
#define HW  32768
#define C_  64
#define CHW (C_*HW)          // 2,097,152
#define MOFF (2*CHW)         // out elements = 4,194,304

// ---------------- mma.sync / ldmatrix / cp.async helpers (sm_80+ PTX) --------
__device__ __forceinline__ uint32_t smem_u32(const void* p) {
    uint32_t a;
    asm("{ .reg .u64 t; cvta.to.shared.u64 t, %1; cvt.u32.u64 %0, t; }" : "=r"(a) : "l"(p));
    return a;
}
__device__ __forceinline__ void ldsm_x4(uint32_t* r, uint32_t addr) {
    asm volatile("ldmatrix.sync.aligned.m8n8.x4.shared.b16 {%0,%1,%2,%3}, [%4];"
        : "=r"(r[0]), "=r"(r[1]), "=r"(r[2]), "=r"(r[3]) : "r"(addr));
}
__device__ __forceinline__ void mma16816(float* d, const uint32_t* a, const uint32_t* b) {
    asm volatile("mma.sync.aligned.m16n8k16.row.col.f32.f16.f16.f32 "
        "{%0,%1,%2,%3}, {%4,%5,%6,%7}, {%8,%9}, {%0,%1,%2,%3};"
        : "+f"(d[0]), "+f"(d[1]), "+f"(d[2]), "+f"(d[3])
        : "r"(a[0]), "r"(a[1]), "r"(a[2]), "r"(a[3]), "r"(b[0]), "r"(b[1]));
}
#define CP16(dst, src, szr) \
    asm volatile("cp.async.cg.shared.global [%0], [%1], 16, %2;" \
        :: "r"(dst), "l"(src), "r"(szr) : "memory")
#define CP_WAIT_ALL() asm volatile("cp.async.wait_all;" ::: "memory")

// fp16 2-term split helpers: hi = rn(v), lo = rn(v - hi)
__device__ __forceinline__ uint32_t pack_hi(float v0, float v1, float& r0, float& r1) {
    __half h0 = __float2half_rn(v0);
    __half h1 = __float2half_rn(v1);
    r0 = v0 - __half2float(h0);
    r1 = v1 - __half2float(h1);
    return ((uint32_t)__half_as_ushort(h1) << 16) | __half_as_ushort(h0);
}
__device__ __forceinline__ uint32_t pack_lo(float r0, float r1) {
    return ((uint32_t)__half_as_ushort(__float2half_rn(r1)) << 16)
         | __half_as_ushort(__float2half_rn(r0));
}

// ---------------- scratch ----------------------------------------------------
__device__ __align__(16) __half g_in_hi [4*HW*C_];   // [img][y][x][ch]
__device__ __align__(16) __half g_in_lo [4*HW*C_];
__device__ __align__(16) __half g_mid_hi[4*HW*C_];
__device__ __align__(16) __half g_mid_lo[4*HW*C_];
__device__ __align__(16) __half g_buf_hi[4*HW*C_];   // residual block out
__device__ __align__(16) __half g_buf_lo[4*HW*C_];
__device__ __align__(16) __half g_att_hi[2*HW*C_];
__device__ __align__(16) __half g_att_lo[2*HW*C_];
__device__ __align__(16) __half g_w1_hi[9*64*64];    // [tap][oc][ch]
__device__ __align__(16) __half g_w2_hi[9*64*64];
__device__ __align__(16) __half g_wq_hi [64*64];     // [oc][ic]
__device__ __align__(16) __half g_wsr_hi[128*64];    // S then R
__device__ __align__(16) __half g_wf_hi [64*128];    // fuse [oc][ic]
__device__ __align__(16) float g_Q[2*HW*C_];         // [p][c] fp32
__device__ __align__(16) float g_S[2*HW*C_];
__device__ __align__(16) float g_R[2*HW*C_];

// ---------------- prep (merged): inputs + all weights ------------------------
__global__ __launch_bounds__(256)
void prep_all(const float* __restrict__ xl, const float* __restrict__ xr,
              const float* __restrict__ w1, const float* __restrict__ w2,
              const float* __restrict__ qw, const float* __restrict__ sw,
              const float* __restrict__ rw, const float* __restrict__ fw)
{
    if (blockIdx.x < 512) {
        const int gp = blockIdx.x*256 + threadIdx.x;   // 0..4*HW-1
        const int n  = gp >> 15, pix = gp & (HW-1);
        const float* src = ((n < 2) ? (xl + n*CHW) : (xr + (n-2)*CHW)) + pix;

        uint32_t hb[32], lb[32];
#pragma unroll
        for (int j = 0; j < 32; j++) {
            float v0 = src[(size_t)(2*j)*HW];
            float v1 = src[(size_t)(2*j+1)*HW];
            float r0, r1;
            hb[j] = pack_hi(v0, v1, r0, r1);
            lb[j] = pack_lo(r0, r1);
        }
        uint4* dh = reinterpret_cast<uint4*>(g_in_hi + (size_t)gp*64);
        uint4* dl = reinterpret_cast<uint4*>(g_in_lo + (size_t)gp*64);
        const uint4* sh = reinterpret_cast<const uint4*>(hb);
        const uint4* sl = reinterpret_cast<const uint4*>(lb);
#pragma unroll
        for (int j = 0; j < 8; j++) { dh[j] = sh[j]; dl[j] = sl[j]; }
    } else {
        const int i = (blockIdx.x - 512)*256 + threadIdx.x;
        if (i < 9*4096) {
            const int tap = i >> 12, r = i & 4095;
            const int oc = r >> 6, ci = r & 63;
            const int src = (oc*64 + ci)*9 + tap;
            const int dst = (tap*64 + oc)*64 + ci;
            g_w1_hi[dst] = __float2half_rn(w1[src]);
            g_w2_hi[dst] = __float2half_rn(w2[src]);
        } else {
            const int j = i - 9*4096;
            if (j >= 20480) return;
            if (j < 4096)       g_wq_hi [j]             = __float2half_rn(qw[j]);
            else if (j < 8192)  g_wsr_hi[j - 4096]      = __float2half_rn(sw[j - 4096]);
            else if (j < 12288) g_wsr_hi[4096 + j-8192] = __float2half_rn(rw[j - 8192]);
            else                g_wf_hi [j - 12288]     = __float2half_rn(fw[j - 12288]);
        }
    }
}

// ---------------- HMMA 3x3 conv: R13 design, 4-row segments (512 CTAs) -------
// CTA = 256 thr (8 warps: 4 M x 2 N), strip = 64 px, segment = 4 rows (2 pairs)
#define APX2  66
#define AROW2 (APX2*128)               // 8448 bytes per plane per half
#define CA_HI 0u
#define CA_LO (4u*AROW2)               // 33792
#define CB_OFF (8u*AROW2)              // 67584
#define SMEM_CONV (CB_OFF + 16384u)    // 83968

__global__ __launch_bounds__(256, 2)
void conv_mma_kernel(const __half* __restrict__ in_hi,
                     const __half* __restrict__ in_lo,
                     const __half* __restrict__ w_hi,
                     const float* __restrict__ xl, const float* __restrict__ xr,
                     int layer)
{
    extern __shared__ __align__(16) char smem[];
    const uint32_t sb = smem_u32(smem);
    const int tid = threadIdx.x;
    const int lane = tid & 31, warp = tid >> 5;
    const int wm = warp & 3, wn = warp >> 2;
    const int mbase = wm*16, ocb = wn*32;
    const int grp = lane >> 3, row = lane & 7;

    const int cta = blockIdx.x;           // 512 CTAs = img(4) x strip(4) x seg(32)
    const int n  = cta >> 7;
    const int x0 = ((cta >> 5) & 3) * 64;
    const int y0 = (cta & 31) * 4;

    auto stage_row = [&](int gy) {
        const uint32_t pl = (uint32_t)((gy + 4) & 3) * AROW2;
        const int cy = gy < 0 ? 0 : (gy >= H_ ? H_-1 : gy);
        for (int i = tid; i < 528; i += 256) {
            const int px = i >> 3, g = i & 7;
            const int gx = x0 + px - 1;
            const bool ok = ((unsigned)gy < (unsigned)H_) && ((unsigned)gx < (unsigned)W_);
            const int cx = gx < 0 ? 0 : (gx >= W_ ? W_-1 : gx);
            const size_t go = (((size_t)(n*H_ + cy))*W_ + cx)*64 + g*8;
            const uint32_t da = pl + px*128 + ((g ^ (px & 7)) << 4);
            const uint32_t sz = ok ? 16u : 0u;
            CP16(sb + CA_HI + da, in_hi + go, sz);
            CP16(sb + CA_LO + da, in_lo + go, sz);
        }
    };
    auto stage_B = [&](int tap, int buf) {
        const uint32_t bdst = CB_OFF + (uint32_t)buf*8192u;
        for (int i = tid; i < 512; i += 256) {
            const int oc = i >> 3, g = i & 7;
            const uint32_t da = bdst + oc*128 + ((g ^ (oc & 7)) << 4);
            const size_t so = ((size_t)(tap*64 + oc))*64 + g*8;
            CP16(sb + da, w_hi + so, 16u);
        }
    };

    stage_row(y0 - 1); stage_row(y0); stage_row(y0 + 1); stage_row(y0 + 2);
    stage_B(0, 0);
    CP_WAIT_ALL();
    __syncthreads();

    for (int p = 0; p < 2; p++) {
        const int yp = y0 + 2*p;

        float d[2][4][4];
#pragma unroll
        for (int t2 = 0; t2 < 2; t2++)
#pragma unroll
            for (int f = 0; f < 4; f++)
#pragma unroll
                for (int j = 0; j < 4; j++) d[t2][f][j] = 0.f;

        for (int tap = 0; tap < 9; tap++) {
            // async prefetches: next tap's B; next pair's rows at taps 3 & 6
            stage_B((tap + 1) % 9, (p + tap + 1) & 1);
            if (p < 1 && tap == 3) stage_row(yp + 3);
            if (p < 1 && tap == 6) stage_row(yp + 4);

            const int dy = tap/3 - 1, dx = tap%3 - 1;
            const uint32_t bcur = CB_OFF + (uint32_t)((p + tap) & 1)*8192u;

#pragma unroll
            for (int ks = 0; ks < 4; ks++) {
                uint32_t Bh[8];
                {
                    const int oc0 = ocb + ((grp >> 1) << 3) + row;
                    const int gB  = 2*ks + (grp & 1);
                    const uint32_t a0 = oc0*128u + ((gB ^ (oc0 & 7)) << 4);
                    ldsm_x4(Bh,     sb + bcur + a0);
                    const int oc1 = oc0 + 16;
                    const uint32_t a1 = oc1*128u + ((gB ^ (oc1 & 7)) << 4);
                    ldsm_x4(Bh + 4, sb + bcur + a1);
                }
#pragma unroll
                for (int t2 = 0; t2 < 2; t2++) {
                    const uint32_t pl = (uint32_t)((yp + t2 + dy + 4) & 3) * AROW2;
                    const int m  = mbase + ((grp & 1) << 3) + row;
                    const int gA = 2*ks + (grp >> 1);
                    const int px = m + dx + 1;
                    const uint32_t aoff = pl + px*128u + ((gA ^ (px & 7)) << 4);
                    uint32_t Ah[4], Al[4];
                    ldsm_x4(Ah, sb + CA_HI + aoff);
                    ldsm_x4(Al, sb + CA_LO + aoff);
#pragma unroll
                    for (int f = 0; f < 4; f++) {
                        mma16816(d[t2][f], Ah, Bh + 2*f);
                        mma16816(d[t2][f], Al, Bh + 2*f);
                    }
                }
            }
            CP_WAIT_ALL();
            __syncthreads();
        }

        // ---- epilogue (registers -> global; no smem) ------------------------
        const int mrow = (lane >> 2);
        const int cpair = 2*(lane & 3);
#pragma unroll
        for (int t2 = 0; t2 < 2; t2++) {
            const int y = yp + t2;
            if (layer == 0) {
#pragma unroll
                for (int f = 0; f < 4; f++) {
#pragma unroll
                    for (int half = 0; half < 2; half++) {
                        float v0 = d[t2][f][2*half+0], v1 = d[t2][f][2*half+1];
                        v0 = v0 > 0.f ? v0 : 0.1f*v0;
                        v1 = v1 > 0.f ? v1 : 0.1f*v1;
                        const int m = mbase + mrow + half*8;
                        const int c = ocb + f*8 + cpair;
                        const size_t o = (((size_t)(n*H_ + y))*W_ + x0 + m)*64 + c;
                        float r0, r1;
                        *reinterpret_cast<uint32_t*>(g_mid_hi + o) = pack_hi(v0, v1, r0, r1);
                        *reinterpret_cast<uint32_t*>(g_mid_lo + o) = pack_lo(r0, r1);
                    }
                }
            } else {
                const float* res = (n < 2) ? (xl + n*CHW) : (xr + (n-2)*CHW);
#pragma unroll
                for (int f = 0; f < 4; f++) {
#pragma unroll
                    for (int half = 0; half < 2; half++) {
                        const int m = mbase + mrow + half*8;
                        const int c = ocb + f*8 + cpair;
                        const int pix = y*W_ + x0 + m;
                        float v0 = d[t2][f][2*half+0] + res[(size_t)c*HW + pix];
                        float v1 = d[t2][f][2*half+1] + res[(size_t)(c+1)*HW + pix];
                        const size_t o = ((size_t)n*HW + pix)*64 + c;
                        float r0, r1;
                        *reinterpret_cast<uint32_t*>(g_buf_hi + o) = pack_hi(v0, v1, r0, r1);
                        *reinterpret_cast<uint32_t*>(g_buf_lo + o) = pack_lo(r0, r1);
                    }
                }
            }
        }
    }
}

// ---------------- merged Q/S/R HMMA GEMM body (K=64) -------------------------
#define QA_HI 0u
#define QA_LO 16384u
#define QB_HI 32768u
#define SMEM_GEMM 49152u

template<int NOC>
__device__ __forceinline__
void gemm_body(char* smem, int bx,
               const __half* __restrict__ a_hi, const __half* __restrict__ a_lo,
               const __half* __restrict__ w_hi,
               const float* __restrict__ biasA, const float* __restrict__ biasB,
               float* __restrict__ outA, float* __restrict__ outB)
{
    const uint32_t sb = smem_u32(smem);
    const int tid = threadIdx.x;
    const int lane = tid & 31, warp = tid >> 5;
    const int wm = warp & 3, wn = warp >> 2;
    constexpr int NW  = NOC/4;
    constexpr int L16 = NW/16;
    constexpr int F8  = NW/8;
    const int mbase = wm*32, ocb = wn*NW;
    const int grp = lane >> 3, row = lane & 7;
    const int p0 = bx * 128;

    for (int i = tid; i < 1024; i += 512) {
        const int px = i >> 3, g = i & 7;
        const uint32_t da = px*128 + ((g ^ (px & 7)) << 4);
        const size_t so = (size_t)(p0+px)*64 + g*8;
        CP16(sb + QA_HI + da, a_hi + so, 16u);
        CP16(sb + QA_LO + da, a_lo + so, 16u);
    }
    for (int i = tid; i < NOC*8; i += 512) {
        const int oc = i >> 3, g = i & 7;
        const uint32_t da = oc*128 + ((g ^ (oc & 7)) << 4);
        const size_t so = (size_t)oc*64 + g*8;
        CP16(sb + QB_HI + da, w_hi + so, 16u);
    }
    CP_WAIT_ALL();
    __syncthreads();

    float d[2][F8][4];
#pragma unroll
    for (int mt = 0; mt < 2; mt++)
#pragma unroll
        for (int f = 0; f < F8; f++)
#pragma unroll
            for (int j = 0; j < 4; j++) d[mt][f][j] = 0.f;

#pragma unroll
    for (int ks = 0; ks < 4; ks++) {
        uint32_t Bh[4*L16];
#pragma unroll
        for (int l = 0; l < L16; l++) {
            const int oc = ocb + l*16 + ((grp >> 1) << 3) + row;
            const int g  = 2*ks + (grp & 1);
            const uint32_t a = oc*128u + ((g ^ (oc & 7)) << 4);
            ldsm_x4(Bh + 4*l, sb + QB_HI + a);
        }
#pragma unroll
        for (int mt = 0; mt < 2; mt++) {
            const int m = mbase + mt*16 + ((grp & 1) << 3) + row;
            const int g = 2*ks + (grp >> 1);
            const uint32_t a = m*128u + ((g ^ (m & 7)) << 4);
            uint32_t Ah[4], Al[4];
            ldsm_x4(Ah, sb + QA_HI + a);
            ldsm_x4(Al, sb + QA_LO + a);
#pragma unroll
            for (int f = 0; f < F8; f++) {
                mma16816(d[mt][f], Ah, Bh + 2*f);
                mma16816(d[mt][f], Al, Bh + 2*f);
            }
        }
    }

#pragma unroll
    for (int mt = 0; mt < 2; mt++) {
#pragma unroll
        for (int f = 0; f < F8; f++) {
#pragma unroll
            for (int half = 0; half < 2; half++) {
                const int m = mbase + mt*16 + (lane >> 2) + half*8;
                const int c = ocb + f*8 + 2*(lane & 3);
                const float* bias = (c < 64) ? biasA : biasB;
                const int col = c & 63;
                float v0 = d[mt][f][2*half+0] + bias[col];
                float v1 = d[mt][f][2*half+1] + bias[col+1];
                float* o = ((c < 64) ? outA : outB) + (size_t)(p0+m)*64 + col;
                *reinterpret_cast<float2*>(o) = make_float2(v0, v1);
            }
        }
    }
}

__global__ __launch_bounds__(512, 2)
void gemm_qsr(const __half* __restrict__ buf_hi, const __half* __restrict__ buf_lo,
              const __half* __restrict__ wq, const __half* __restrict__ wsr,
              const float* __restrict__ qb, const float* __restrict__ sbias,
              const float* __restrict__ rbias,
              float* __restrict__ Q, float* __restrict__ S, float* __restrict__ R)
{
    extern __shared__ __align__(16) char smem[];
    if (blockIdx.x < 512) {
        gemm_body<64>(smem, blockIdx.x, buf_hi, buf_lo, wq, qb, qb, Q, Q);
    } else {
        gemm_body<128>(smem, blockIdx.x - 512,
                       buf_hi + (size_t)2*HW*64, buf_lo + (size_t)2*HW*64,
                       wsr, sbias, rbias, S, R);
    }
}

// ---------------- attention: warp per pixel, K = 16, MLP-batched gathers -----
__global__ __launch_bounds__(256)
void attn_kernel(const int* __restrict__ xxs, const int* __restrict__ yys,
                 float* __restrict__ outM)
{
    const unsigned FULL = 0xffffffffu;
    const int warp = threadIdx.x >> 5, lane = threadIdx.x & 31;
    const int gp = blockIdx.x*8 + warp;
    const int b  = gp >> 15;

    const float2 q = reinterpret_cast<const float2*>(g_Q + (size_t)gp*64)[lane];

    int idx = 0;
    if (lane < 16) {
        int i = gp*16 + lane;
        idx = xxs[i]*W_ + yys[i];
    }
    int ids[16];
#pragma unroll
    for (int k = 0; k < 16; k++) ids[k] = __shfl_sync(FULL, idx, k);

    const float* Sb = g_S + (size_t)b*HW*64;
    const float* Rb = g_R + (size_t)b*HW*64;

    // batched gathers: all 16 S rows in flight (MLP=16)
    float2 kv[16];
#pragma unroll
    for (int k = 0; k < 16; k++)
        kv[k] = reinterpret_cast<const float2*>(Sb + (size_t)ids[k]*64)[lane];

    float myscore = -1e30f;
#pragma unroll
    for (int k = 0; k < 16; k++) {
        float s = q.x*kv[k].x + q.y*kv[k].y;
#pragma unroll
        for (int off = 16; off; off >>= 1) s += __shfl_xor_sync(FULL, s, off);
        if (lane == k) myscore = s;
    }
    float mx = myscore;
#pragma unroll
    for (int off = 8; off; off >>= 1) mx = fmaxf(mx, __shfl_xor_sync(FULL, mx, off));
    float e = expf(myscore - mx);
    float sum = e;
#pragma unroll
    for (int off = 8; off; off >>= 1) sum += __shfl_xor_sync(FULL, sum, off);
    float m = e / sum;

    // batched gathers: all 16 R rows in flight
    float2 vv[16];
#pragma unroll
    for (int k = 0; k < 16; k++)
        vv[k] = reinterpret_cast<const float2*>(Rb + (size_t)ids[k]*64)[lane];

    float2 accv = make_float2(0.f, 0.f);
#pragma unroll
    for (int k = 0; k < 16; k++) {
        float mk = __shfl_sync(FULL, m, k);
        accv.x = fmaf(mk, vv[k].x, accv.x);
        accv.y = fmaf(mk, vv[k].y, accv.y);
    }
    float r0, r1;
    const size_t o = (size_t)gp*64 + 2*lane;
    *reinterpret_cast<uint32_t*>(g_att_hi + o) = pack_hi(accv.x, accv.y, r0, r1);
    *reinterpret_cast<uint32_t*>(g_att_lo + o) = pack_lo(r0, r1);
    if (lane < 16) outM[(size_t)gp*16 + lane] = m;
}

// ---------------- fusion 1x1 HMMA: K=128 (attn 64 + x_left 64) -> 64 oc ------
#define FA_HI 0u
#define FA_LO 32768u
#define FB_HI 65536u
#define SMEM_FUSE 81920u

__global__ __launch_bounds__(512, 2)
void fuse_hmma(const float* __restrict__ fb, float* __restrict__ out)
{
    extern __shared__ __align__(16) char smem[];
    const uint32_t sb = smem_u32(smem);
    const int tid = threadIdx.x;
    const int lane = tid & 31, warp = tid >> 5;
    const int wm = warp & 3, wn = warp >> 2;
    const int mbase = wm*32, ocb = wn*16;
    const int grp = lane >> 3, row = lane & 7;
    const int p0 = blockIdx.x * 128;

    for (int i = tid; i < 2048; i += 512) {
        const int px = i >> 4, g = i & 15;
        const uint32_t da = px*256 + ((g ^ (px & 7)) << 4);
        const size_t so = (size_t)(p0+px)*64 + (g & 7)*8;
        const __half* sh = (g < 8) ? (g_att_hi + so) : (g_in_hi + so);
        const __half* sl = (g < 8) ? (g_att_lo + so) : (g_in_lo + so);
        CP16(sb + FA_HI + da, sh, 16u);
        CP16(sb + FA_LO + da, sl, 16u);
    }
    for (int i = tid; i < 1024; i += 512) {
        const int oc = i >> 4, g = i & 15;
        const uint32_t da = oc*256 + ((g ^ (oc & 7)) << 4);
        const size_t so = (size_t)oc*128 + g*8;
        CP16(sb + FB_HI + da, g_wf_hi + so, 16u);
    }
    CP_WAIT_ALL();
    __syncthreads();

    float d[2][2][4];
#pragma unroll
    for (int mt = 0; mt < 2; mt++)
#pragma unroll
        for (int f = 0; f < 2; f++)
#pragma unroll
            for (int j = 0; j < 4; j++) d[mt][f][j] = 0.f;

#pragma unroll
    for (int ks = 0; ks < 8; ks++) {
        uint32_t Bh[4];
        {
            const int oc = ocb + ((grp >> 1) << 3) + row;
            const int g  = 2*ks + (grp & 1);
            const uint32_t a = oc*256u + ((g ^ (oc & 7)) << 4);
            ldsm_x4(Bh, sb + FB_HI + a);
        }
#pragma unroll
        for (int mt = 0; mt < 2; mt++) {
            const int m = mbase + mt*16 + ((grp & 1) << 3) + row;
            const int g = 2*ks + (grp >> 1);
            const uint32_t a = m*256u + ((g ^ (m & 7)) << 4);
            uint32_t Ah[4], Al[4];
            ldsm_x4(Ah, sb + FA_HI + a);
            ldsm_x4(Al, sb + FA_LO + a);
#pragma unroll
            for (int f = 0; f < 2; f++) {
                mma16816(d[mt][f], Ah, Bh + 2*f);
                mma16816(d[mt][f], Al, Bh + 2*f);
            }
        }
    }
    __syncthreads();

    float* sf = reinterpret_cast<float*>(smem);    // [64][132]
#pragma unroll
    for (int mt = 0; mt < 2; mt++) {
#pragma unroll
        for (int f = 0; f < 2; f++) {
#pragma unroll
            for (int half = 0; half < 2; half++) {
                const int m = mbase + mt*16 + (lane >> 2) + half*8;
                const int c = ocb + f*8 + 2*(lane & 3);
                sf[(c+0)*132 + m] = d[mt][f][2*half+0];
                sf[(c+1)*132 + m] = d[mt][f][2*half+1];
            }
        }
    }
    __syncthreads();
    const int img = p0 >> 15, pix0 = p0 & (HW-1);
    for (int i = tid; i < 8192; i += 512) {
        const int c = i >> 7, px = i & 127;
        out[(size_t)img*CHW + (size_t)c*HW + pix0 + px] = sf[c*132 + px] + fb[c];
    }
}

// -----------------------------------------------------------------------------
extern "C" void kernel_launch(void* const* d_in, const int* in_sizes, int n_in,
                              void* d_out, int out_size)
{
    const float* xl    = (const float*)d_in[0];
    const float* xr    = (const float*)d_in[1];
    const int*   xxs   = (const int*)  d_in[2];
    const int*   yys   = (const int*)  d_in[3];
    const float* rb_w1 = (const float*)d_in[5];
    const float* rb_w2 = (const float*)d_in[6];
    const float* b1_w  = (const float*)d_in[7];
    const float* b1_b  = (const float*)d_in[8];
    const float* b2_w  = (const float*)d_in[9];
    const float* b2_b  = (const float*)d_in[10];
    const float* b3_w  = (const float*)d_in[11];
    const float* b3_b  = (const float*)d_in[12];
    const float* fus_w = (const float*)d_in[13];
    const float* fus_b = (const float*)d_in[14];
    float* out = (float*)d_out;

    static int attr_set = 0;
    if (!attr_set) {
        cudaFuncSetAttribute(conv_mma_kernel,
                             cudaFuncAttributeMaxDynamicSharedMemorySize, SMEM_CONV);
        cudaFuncSetAttribute(gemm_qsr,
                             cudaFuncAttributeMaxDynamicSharedMemorySize, SMEM_GEMM);
        cudaFuncSetAttribute(fuse_hmma,
                             cudaFuncAttributeMaxDynamicSharedMemorySize, SMEM_FUSE);
        attr_set = 1;
    }

    __half *p_in_hi, *p_in_lo, *p_mid_hi, *p_mid_lo;
    __half *p_w1h, *p_w2h;
    __half *p_bh, *p_bl, *p_wqh, *p_wsrh;
    float *p_Q, *p_S, *p_R;
    cudaGetSymbolAddress((void**)&p_in_hi,  g_in_hi);
    cudaGetSymbolAddress((void**)&p_in_lo,  g_in_lo);
    cudaGetSymbolAddress((void**)&p_mid_hi, g_mid_hi);
    cudaGetSymbolAddress((void**)&p_mid_lo, g_mid_lo);
    cudaGetSymbolAddress((void**)&p_w1h, g_w1_hi);
    cudaGetSymbolAddress((void**)&p_w2h, g_w2_hi);
    cudaGetSymbolAddress((void**)&p_bh,  g_buf_hi);
    cudaGetSymbolAddress((void**)&p_bl,  g_buf_lo);
    cudaGetSymbolAddress((void**)&p_wqh, g_wq_hi);
    cudaGetSymbolAddress((void**)&p_wsrh, g_wsr_hi);
    cudaGetSymbolAddress((void**)&p_Q, g_Q);
    cudaGetSymbolAddress((void**)&p_S, g_S);
    cudaGetSymbolAddress((void**)&p_R, g_R);

    prep_all<<<736, 256>>>(xl, xr, rb_w1, rb_w2, b1_w, b2_w, b3_w, fus_w);

    conv_mma_kernel<<<512, 256, SMEM_CONV>>>(p_in_hi,  p_in_lo,  p_w1h, xl, xr, 0);
    conv_mma_kernel<<<512, 256, SMEM_CONV>>>(p_mid_hi, p_mid_lo, p_w2h, xl, xr, 1);

    gemm_qsr<<<1024, 512, SMEM_GEMM>>>(p_bh, p_bl, p_wqh, p_wsrh,
                                       b1_b, b2_b, b3_b, p_Q, p_S, p_R);

    attn_kernel<<<8192, 256>>>(xxs, yys, out + MOFF);
    fuse_hmma<<<512, 512, SMEM_FUSE>>>(fus_b, out);
}